// round 8
// baseline (speedup 1.0000x reference)
#include <cuda_runtime.h>
#include <math.h>
#include <stdint.h>

// ---------------- problem constants (fixed shapes) ----------------
#define BQ   16
#define CH   256
#define CONDC 512
#define TT   2048
#define TSL  512
#define NH   4
#define KC   64

#define SA 136       // padded smem stride (words): mod 32 = 8, *4 % 16 == 0

// ---------------- scratch (device globals; no allocation) ----------------
__device__ float g_c  [BQ * CH * TSL];        // cond proj (tf32 bits)   [b][C][Ts]
__device__ float g_q  [BQ * CH * TT];         // q: fp32 -> rope_q -> tf32 bits
__device__ float g_k  [BQ * CH * TSL];        // k: fp32 -> rope_k -> tf32 bits
__device__ float g_v  [BQ * CH * TSL];        // v (tf32 bits)
__device__ float g_att[BQ * CH * TT];         // attn out (tf32 bits)
__device__ float g_y  [BQ * CH * TT];         // wo proj (tf32 bits)
__device__ float g_xt [BQ * CH * TT];         // x pre-converted tf32 bits
__device__ float g_cl [BQ * CONDC * TSL];     // cond_latent tf32 bits
__device__ float g_wt [6 * 131072];           // converted weights (see offsets)
__device__ float g_cos[32 * TT];              // [d][t]
__device__ float g_sin[32 * TT];

// weight offsets in g_wt (words)
#define W_COND 0
#define W_Q    131072
#define W_K    196608
#define W_V    262144
#define W_O    327680
#define W_FILM 393216

// ---------------- tf32 helpers ----------------
__device__ __forceinline__ uint32_t f2tf(float f) {
    uint32_t u;
    asm("cvt.rna.tf32.f32 %0, %1;" : "=r"(u) : "f"(f));
    return u;
}
__device__ __forceinline__ float f2tf_f(float f) { return __uint_as_float(f2tf(f)); }

__device__ __forceinline__ void mma_tf32(float* c, const uint32_t* a, const uint32_t* b) {
    asm volatile(
        "mma.sync.aligned.m16n8k8.row.col.f32.tf32.tf32.f32 "
        "{%0,%1,%2,%3}, {%4,%5,%6,%7}, {%8,%9}, {%0,%1,%2,%3};\n"
        : "+f"(c[0]), "+f"(c[1]), "+f"(c[2]), "+f"(c[3])
        : "r"(a[0]), "r"(a[1]), "r"(a[2]), "r"(a[3]), "r"(b[0]), "r"(b[1]));
}

// ---------------- RoPE tables, layout [d][t] ----------------
__global__ void rope_table_kernel() {
    int idx = blockIdx.x * blockDim.x + threadIdx.x;
    if (idx >= 32 * TT) return;
    int d = idx / TT;
    int t = idx % TT;
    float invf = (float)pow(10000.0, -(double)d / 32.0);
    float ang  = (float)t * invf;            // same fp32 rounding as reference
    g_cos[idx] = (float)cos((double)ang);
    g_sin[idx] = (float)sin((double)ang);
}

// ---------------- generic fp32 -> tf32-bits convert (n % 4 == 0) ----------
__global__ void cvt_kernel(const float* __restrict__ src, float* __restrict__ dst, int n4) {
    int i = blockIdx.x * blockDim.x + threadIdx.x;
    if (i >= n4) return;
    float4 v = *(const float4*)(src + (size_t)i * 4);
    float4 o;
    o.x = f2tf_f(v.x); o.y = f2tf_f(v.y); o.z = f2tf_f(v.z); o.w = f2tf_f(v.w);
    *(float4*)(dst + (size_t)i * 4) = o;
}

// ---------------- convert all 6 weight matrices in one launch -------------
__global__ void cvt_weights_kernel(const float* __restrict__ wc, const float* __restrict__ wq,
                                   const float* __restrict__ wk, const float* __restrict__ wv,
                                   const float* __restrict__ wo, const float* __restrict__ wf) {
    int seg = blockIdx.y;
    const float* src; float* dst; int n;
    switch (seg) {
        case 0: src = wc; dst = g_wt + W_COND; n = 131072; break;
        case 1: src = wq; dst = g_wt + W_Q;    n = 65536;  break;
        case 2: src = wk; dst = g_wt + W_K;    n = 65536;  break;
        case 3: src = wv; dst = g_wt + W_V;    n = 65536;  break;
        case 4: src = wo; dst = g_wt + W_O;    n = 65536;  break;
        default: src = wf; dst = g_wt + W_FILM; n = 131072; break;
    }
    int i = blockIdx.x * blockDim.x + threadIdx.x;
    if (i * 4 >= n) return;
    float4 v = *(const float4*)(src + (size_t)i * 4);
    float4 o;
    o.x = f2tf_f(v.x); o.y = f2tf_f(v.y); o.z = f2tf_f(v.z); o.w = f2tf_f(v.w);
    *(float4*)(dst + (size_t)i * 4) = o;
}

// ---------------- rope + mask K in place -> tf32 bits ----------------
__global__ void rope_k_mask_kernel(float* __restrict__ k, const float* __restrict__ cmask) {
    int idx = blockIdx.x * blockDim.x + threadIdx.x;
    if (idx >= BQ * NH * 32 * TSL) return;
    int t  = idx & (TSL - 1);
    int rr = idx >> 9;
    int d  = rr & 31;
    int bh = rr >> 5;
    int b  = bh >> 2;
    float cs = g_cos[d * TT + t];
    float sn = g_sin[d * TT + t];
    float cm = cmask[(size_t)b * TSL + t];
    size_t base = ((size_t)bh * KC + d) * TSL + t;
    float k1 = k[base];
    float k2 = k[base + (size_t)32 * TSL];
    k[base]                    = f2tf_f((k1 * cs - k2 * sn) * cm);
    k[base + (size_t)32 * TSL] = f2tf_f((k2 * cs + k1 * sn) * cm);
}

// ---------------- rope Q in place -> tf32 bits ----------------
__global__ void rope_q_kernel(float* __restrict__ q) {
    int idx = blockIdx.x * blockDim.x + threadIdx.x;
    if (idx >= BQ * NH * 32 * TT) return;
    int t  = idx & (TT - 1);
    int rr = idx >> 11;
    int d  = rr & 31;
    int bh = rr >> 5;
    float cs = g_cos[d * TT + t];
    float sn = g_sin[d * TT + t];
    size_t base = ((size_t)bh * KC + d) * TT + t;
    float q1 = q[base];
    float q2 = q[base + (size_t)32 * TT];
    q[base]                   = f2tf_f(q1 * cs - q2 * sn);
    q[base + (size_t)32 * TT] = f2tf_f(q2 * cs + q1 * sn);
}

// ============================================================================
// tf32 MMA GEMM, 128x128 CTA tile, 256 threads, warp tile 64x32, BK=32,
// double-buffered dynamic smem. Inputs are PRE-CONVERTED tf32 bits -> loaders
// are pure bit copies (no CVT in the mainloop).
// outcvt: store f2tf(acc+bias) bits (output consumed only as MMA operand).
// GSEL: 0 = plain; 1 = kv-fused (blockIdx.z>>4 selects set; k fp32, v tf32).
// ============================================================================
#define GEMM_SMEM (4 * 32 * SA * 4)

template<int GSEL>
__global__ __launch_bounds__(256, 2)
void mma_gemm64(const float* __restrict__ A0, const float* __restrict__ A1,
                const float* __restrict__ B,
                const float* __restrict__ bias0, const float* __restrict__ bias1,
                float* __restrict__ Y0, float* __restrict__ Y1,
                int Ndim, int Kdim, size_t strideB, size_t strideY, int outcvt0)
{
    extern __shared__ uint32_t smg[];
    uint32_t* Asm = smg;                 // [2][32*SA]
    uint32_t* Bsm = smg + 2 * 32 * SA;   // [2][32*SA]

    const int tid = threadIdx.x;
    int bz, sel = 0;
    if (GSEL == 1) { bz = blockIdx.z & 15; sel = blockIdx.z >> 4; }
    else           { bz = blockIdx.z; }
    const float* A    = (GSEL == 1 && sel) ? A1 : A0;
    const float* bias = (GSEL == 1 && sel) ? bias1 : bias0;
    float*       Y    = (GSEL == 1 && sel) ? Y1 : Y0;
    const int outcvt  = (GSEL == 1) ? sel : outcvt0;   // kv: k fp32, v tf32
    const float* Bb = B + (size_t)bz * strideB;
    float*       Yb = Y + (size_t)bz * strideY;
    const int m0 = blockIdx.y * 128, n0 = blockIdx.x * 128;

    const int wid = tid >> 5, lane = tid & 31;
    const int wm = wid >> 2, wn = wid & 3;       // 2x4 warp grid, 64x32 warp tile
    const int r = lane >> 2, c = lane & 3;

    const int a_m = ((tid >> 1) + ((tid & 1) << 4)) & 127;
    const int a_k = (tid & 1) << 4;
    const int b_row = tid >> 3;          // 0..31
    const int b_c4  = (tid & 7) * 4;     // 0..28

    float acc[4][4][4] = {};
    const int nk = Kdim / 32;

    uint4 avr[4], bvr[4];
#define LDG_T(k0)                                                                       \
    {                                                                                   \
        _Pragma("unroll")                                                               \
        for (int j = 0; j < 4; ++j) {                                                   \
            avr[j] = *(const uint4*)&A[(size_t)(m0 + a_m) * Kdim + (k0) + a_k + 4 * j]; \
            bvr[j] = *(const uint4*)&Bb[(size_t)((k0) + b_row) * Ndim + n0 + b_c4 + 32 * j]; \
        }                                                                               \
    }
#define STS_T(buf)                                                                      \
    {                                                                                   \
        uint32_t* Ab = Asm + (buf) * 32 * SA;                                           \
        uint32_t* Bd = Bsm + (buf) * 32 * SA;                                           \
        _Pragma("unroll")                                                               \
        for (int j = 0; j < 4; ++j) {                                                   \
            Ab[(a_k + 4 * j + 0) * SA + a_m] = avr[j].x;                                \
            Ab[(a_k + 4 * j + 1) * SA + a_m] = avr[j].y;                                \
            Ab[(a_k + 4 * j + 2) * SA + a_m] = avr[j].z;                                \
            Ab[(a_k + 4 * j + 3) * SA + a_m] = avr[j].w;                                \
            *(uint4*)&Bd[b_row * SA + b_c4 + 32 * j] = bvr[j];                          \
        }                                                                               \
    }

    LDG_T(0);
    STS_T(0);
    __syncthreads();

    for (int kb = 0; kb < nk; ++kb) {
        const int cur = kb & 1;
        const bool more = (kb + 1 < nk);
        if (more) LDG_T((kb + 1) * 32);

        const uint32_t* Ac = Asm + cur * 32 * SA;
        const uint32_t* Bc = Bsm + cur * 32 * SA;
#pragma unroll
        for (int k8 = 0; k8 < 32; k8 += 8) {
            uint32_t af[4][4], bf[4][2];
#pragma unroll
            for (int mt = 0; mt < 4; ++mt) {
                int mb = wm * 64 + mt * 16 + r;
                af[mt][0] = Ac[(k8 + c) * SA + mb];
                af[mt][1] = Ac[(k8 + c) * SA + mb + 8];
                af[mt][2] = Ac[(k8 + c + 4) * SA + mb];
                af[mt][3] = Ac[(k8 + c + 4) * SA + mb + 8];
            }
#pragma unroll
            for (int nt = 0; nt < 4; ++nt) {
                int nb = wn * 32 + nt * 8 + r;
                bf[nt][0] = Bc[(k8 + c) * SA + nb];
                bf[nt][1] = Bc[(k8 + c + 4) * SA + nb];
            }
#pragma unroll
            for (int mt = 0; mt < 4; ++mt)
#pragma unroll
                for (int nt = 0; nt < 4; ++nt)
                    mma_tf32(acc[mt][nt], af[mt], bf[nt]);
        }
        if (more) STS_T(cur ^ 1);
        __syncthreads();
    }
#undef LDG_T
#undef STS_T

#pragma unroll
    for (int mt = 0; mt < 4; ++mt) {
#pragma unroll
        for (int h = 0; h < 2; ++h) {
            const int row = m0 + wm * 64 + mt * 16 + h * 8 + r;
            float bval = bias[row];
#pragma unroll
            for (int nt = 0; nt < 4; ++nt) {
                const int col = n0 + wn * 32 + nt * 8 + c * 2;
                float2 o;
                if (outcvt) {
                    o.x = f2tf_f(acc[mt][nt][h * 2 + 0] + bval);
                    o.y = f2tf_f(acc[mt][nt][h * 2 + 1] + bval);
                } else {
                    o.x = acc[mt][nt][h * 2 + 0] + bval;
                    o.y = acc[mt][nt][h * 2 + 1] + bval;
                }
                *(float2*)&Yb[(size_t)row * Ndim + col] = o;
            }
        }
    }
}

// ============================================================================
// Fused flash attention. Q/K/V arrive as tf32 bits (pre-roped/masked) ->
// all smem fills are vectorized bit copies. Output att stored as tf32 bits.
// ============================================================================
#define FSA 136
#define FSK 72
#define FSV 68
#define FLASH_SMEM ((64*FSA + 64*FSK + 64*FSV + 64*FSA + 512) * 4)

__global__ __launch_bounds__(256, 2)
void flash_attn(const float* __restrict__ Qg, const float* __restrict__ Kg,
                const float* __restrict__ Vg, const float* __restrict__ cmask,
                float* __restrict__ O)
{
    extern __shared__ uint32_t sm[];
    uint32_t* Qs  = sm;                    // [64][136]
    uint32_t* Ks  = sm + 64 * FSA;         // [64][72]   [d][n]
    uint32_t* Vs  = Ks + 64 * FSK;         // [64][68]   [ch][pos]
    uint32_t* Ps  = Vs + 64 * FSV;         // [64][136]
    float*    cmb = (float*)(Ps + 64 * FSA);  // [512] additive bias

    const int bh = blockIdx.z;
    const int b  = bh >> 2;
    const int m0 = blockIdx.y * 128;
    const int tid = threadIdx.x, wid = tid >> 5, lane = tid & 31;
    const int r = lane >> 2, c = lane & 3;
    const int mb = wid * 16 + r;

    const float* Qb = Qg + (size_t)bh * KC * TT;
    const float* Kb = Kg + (size_t)bh * KC * TSL;
    const float* Vb = Vg + (size_t)bh * KC * TSL;

    // ---- load Q tile (64 x 128): pure bit copy ----
    {
        int row  = tid >> 2;          // 0..63
        int colb = (tid & 3) * 4;
#pragma unroll
        for (int j = 0; j < 8; ++j) {
            int m = colb + 16 * j;
            *(uint4*)&Qs[row * FSA + m] = *(const uint4*)&Qb[(size_t)row * TT + m0 + m];
        }
    }
    // ---- cmask -> additive bias in smem ----
    for (int i = tid; i < TSL; i += 256)
        cmb[i] = (cmask[(size_t)b * TSL + i] == 0.f) ? -1e4f : 0.f;

    // ---- prefetch chunk 0 ----
    const int prow = tid >> 2;          // 0..63
    const int pcol = (tid & 3) * 4;
    uint4 kr[4], vr[4];
#pragma unroll
    for (int j = 0; j < 4; ++j) {
        kr[j] = *(const uint4*)&Kb[(size_t)prow * TSL + pcol + 16 * j];
        vr[j] = *(const uint4*)&Vb[(size_t)prow * TSL + pcol + 16 * j];
    }

    float m_run[2] = {-1e30f, -1e30f};
    float l_run[2] = {0.f, 0.f};
    float acc_o[8][4] = {};

    __syncthreads();

    for (int ci = 0; ci < 8; ++ci) {
        const int s0 = ci * 64;
#pragma unroll
        for (int j = 0; j < 4; ++j) {
            int col = pcol + 16 * j;
            *(uint4*)&Ks[prow * FSK + col] = kr[j];
            *(uint4*)&Vs[prow * FSV + col] = vr[j];
        }
        __syncthreads();
        if (ci < 7) {
#pragma unroll
            for (int j = 0; j < 4; ++j) {
                kr[j] = *(const uint4*)&Kb[(size_t)prow * TSL + s0 + 64 + pcol + 16 * j];
                vr[j] = *(const uint4*)&Vb[(size_t)prow * TSL + s0 + 64 + pcol + 16 * j];
            }
        }

        // ---- S = Q^T K : warp tile 16 x 64 ----
        float acc_s[8][4] = {};
#pragma unroll
        for (int k8 = 0; k8 < 64; k8 += 8) {
            uint32_t af[4];
            af[0] = Qs[(k8 + c) * FSA + mb];
            af[1] = Qs[(k8 + c) * FSA + mb + 8];
            af[2] = Qs[(k8 + c + 4) * FSA + mb];
            af[3] = Qs[(k8 + c + 4) * FSA + mb + 8];
#pragma unroll
            for (int nt = 0; nt < 8; ++nt) {
                uint32_t bf[2];
                bf[0] = Ks[(k8 + c) * FSK + nt * 8 + r];
                bf[1] = Ks[(k8 + c + 4) * FSK + nt * 8 + r];
                mma_tf32(acc_s[nt], af, bf);
            }
        }

        // ---- scale + bias + online softmax ----
        float mx[2] = {-1e30f, -1e30f};
#pragma unroll
        for (int nt = 0; nt < 8; ++nt) {
            float2 bias = *(float2*)&cmb[s0 + nt * 8 + 2 * c];
#pragma unroll
            for (int jj = 0; jj < 4; ++jj) {
                float v = acc_s[nt][jj] * 0.125f + ((jj & 1) ? bias.y : bias.x);
                acc_s[nt][jj] = v;
                mx[jj >> 1] = fmaxf(mx[jj >> 1], v);
            }
        }
#pragma unroll
        for (int h = 0; h < 2; ++h) {
            mx[h] = fmaxf(mx[h], __shfl_xor_sync(0xffffffffu, mx[h], 1));
            mx[h] = fmaxf(mx[h], __shfl_xor_sync(0xffffffffu, mx[h], 2));
        }
        float mnew[2], scale[2], lad[2] = {0.f, 0.f};
#pragma unroll
        for (int h = 0; h < 2; ++h) {
            mnew[h]  = fmaxf(m_run[h], mx[h]);
            scale[h] = __expf(m_run[h] - mnew[h]);
            m_run[h] = mnew[h];
        }
#pragma unroll
        for (int nt = 0; nt < 8; ++nt) {
#pragma unroll
            for (int jj = 0; jj < 4; ++jj) {
                float e = __expf(acc_s[nt][jj] - mnew[jj >> 1]);
                acc_s[nt][jj] = e;
                lad[jj >> 1] += e;
            }
        }
#pragma unroll
        for (int h = 0; h < 2; ++h) {
            lad[h] += __shfl_xor_sync(0xffffffffu, lad[h], 1);
            lad[h] += __shfl_xor_sync(0xffffffffu, lad[h], 2);
            l_run[h] = l_run[h] * scale[h] + lad[h];
        }
#pragma unroll
        for (int nt = 0; nt < 8; ++nt) {
#pragma unroll
            for (int jj = 0; jj < 4; ++jj)
                acc_o[nt][jj] *= scale[jj >> 1];
        }
        // P -> smem [k][m]
#pragma unroll
        for (int nt = 0; nt < 8; ++nt) {
#pragma unroll
            for (int jj = 0; jj < 4; ++jj) {
                int kcol = nt * 8 + 2 * c + (jj & 1);
                int mrow = wid * 16 + r + (jj >> 1) * 8;
                Ps[kcol * FSA + mrow] = f2tf(acc_s[nt][jj]);
            }
        }
        __syncwarp();

        // ---- O += P @ V^T ----
#pragma unroll
        for (int k8 = 0; k8 < 64; k8 += 8) {
            uint32_t af[4];
            af[0] = Ps[(k8 + c) * FSA + mb];
            af[1] = Ps[(k8 + c) * FSA + mb + 8];
            af[2] = Ps[(k8 + c + 4) * FSA + mb];
            af[3] = Ps[(k8 + c + 4) * FSA + mb + 8];
#pragma unroll
            for (int nt = 0; nt < 8; ++nt) {
                uint32_t bf[2];
                bf[0] = Vs[(nt * 8 + r) * FSV + k8 + c];
                bf[1] = Vs[(nt * 8 + r) * FSV + k8 + c + 4];
                mma_tf32(acc_o[nt], af, bf);
            }
        }
        __syncthreads();
    }

    // ---- epilogue: /l, tf32-round (att is only an MMA operand), store ----
    float inv[2] = {1.f / l_run[0], 1.f / l_run[1]};
    float* Pf = (float*)Ps;
#pragma unroll
    for (int nt = 0; nt < 8; ++nt) {
#pragma unroll
        for (int jj = 0; jj < 4; ++jj) {
            int n = nt * 8 + 2 * c + (jj & 1);
            int m = wid * 16 + r + (jj >> 1) * 8;
            Pf[n * FSA + m] = f2tf_f(acc_o[nt][jj] * inv[jj >> 1]);
        }
    }
    __syncthreads();
    {
        int row = tid >> 2;
        int mq  = (tid & 3) * 4;
#pragma unroll
        for (int j = 0; j < 8; ++j) {
            int m = mq + 16 * j;
            *(float4*)&O[((size_t)bh * KC + row) * TT + m0 + m] =
                *(float4*)&Pf[row * FSA + m];
        }
    }
}

// ============================================================================
// Fused FiLM GEMM — pre-converted inputs, no CVT in mainloop.
// ============================================================================
#define FILM_SMEM ((3 * 2 * 16 * SA) * 4)

__global__ __launch_bounds__(512)
void film_gemm(const float* __restrict__ Wf, const float* __restrict__ Yin,
               const float* __restrict__ bfilm, const float* __restrict__ x,
               const float* __restrict__ xmask, float* __restrict__ out)
{
    extern __shared__ uint32_t smf[];
    uint32_t* AsG = smf;
    uint32_t* AsB = smf + 2 * 16 * SA;
    uint32_t* Bs  = smf + 4 * 16 * SA;

    const int tid = threadIdx.x;
    const int bz  = blockIdx.z;
    const float* Bb = Yin + (size_t)bz * CH * TT;
    const int m0 = blockIdx.y * 128, n0 = blockIdx.x * 128;

    const int wid = tid >> 5, lane = tid & 31;
    const int wm = wid >> 2, wn = wid & 3;
    const int r = lane >> 2, c = lane & 3;

    const int l_row = tid >> 5;
    const int l_col = lane * 4;
    const int l_am  = tid >> 2;
    const int l_ak  = (tid & 3) * 4;

    float acc_g[2][4][4] = {};
    float acc_b[2][4][4] = {};

    uint4 bvr, agr, abr;
#define LDG_TILE_F(k0)                                                                  \
    {                                                                                   \
        bvr = *(const uint4*)&Bb[(size_t)((k0) + l_row) * TT + n0 + l_col];             \
        agr = *(const uint4*)&Wf[(size_t)(m0 + l_am) * CH + (k0) + l_ak];               \
        abr = *(const uint4*)&Wf[(size_t)(256 + m0 + l_am) * CH + (k0) + l_ak];         \
    }
#define STS_TILE_F(buf)                                                                 \
    {                                                                                   \
        *(uint4*)&Bs[(buf) * 16 * SA + l_row * SA + l_col] = bvr;                       \
        AsG[(buf) * 16 * SA + (l_ak + 0) * SA + l_am] = agr.x;                          \
        AsG[(buf) * 16 * SA + (l_ak + 1) * SA + l_am] = agr.y;                          \
        AsG[(buf) * 16 * SA + (l_ak + 2) * SA + l_am] = agr.z;                          \
        AsG[(buf) * 16 * SA + (l_ak + 3) * SA + l_am] = agr.w;                          \
        AsB[(buf) * 16 * SA + (l_ak + 0) * SA + l_am] = abr.x;                          \
        AsB[(buf) * 16 * SA + (l_ak + 1) * SA + l_am] = abr.y;                          \
        AsB[(buf) * 16 * SA + (l_ak + 2) * SA + l_am] = abr.z;                          \
        AsB[(buf) * 16 * SA + (l_ak + 3) * SA + l_am] = abr.w;                          \
    }

    LDG_TILE_F(0);
    STS_TILE_F(0);
    __syncthreads();

    const int nk = CH / 16;
    for (int kb = 0; kb < nk; ++kb) {
        const int cur = kb & 1;
        const bool more = (kb + 1 < nk);
        if (more) LDG_TILE_F((kb + 1) * 16);

#pragma unroll
        for (int k8 = 0; k8 < 16; k8 += 8) {
            uint32_t afg[2][4], afb[2][4], bf[4][2];
#pragma unroll
            for (int mt = 0; mt < 2; ++mt) {
                int mbx = wm * 32 + mt * 16 + r;
                afg[mt][0] = AsG[cur * 16 * SA + (k8 + c) * SA + mbx];
                afg[mt][1] = AsG[cur * 16 * SA + (k8 + c) * SA + mbx + 8];
                afg[mt][2] = AsG[cur * 16 * SA + (k8 + c + 4) * SA + mbx];
                afg[mt][3] = AsG[cur * 16 * SA + (k8 + c + 4) * SA + mbx + 8];
                afb[mt][0] = AsB[cur * 16 * SA + (k8 + c) * SA + mbx];
                afb[mt][1] = AsB[cur * 16 * SA + (k8 + c) * SA + mbx + 8];
                afb[mt][2] = AsB[cur * 16 * SA + (k8 + c + 4) * SA + mbx];
                afb[mt][3] = AsB[cur * 16 * SA + (k8 + c + 4) * SA + mbx + 8];
            }
#pragma unroll
            for (int nt = 0; nt < 4; ++nt) {
                int nb = wn * 32 + nt * 8 + r;
                bf[nt][0] = Bs[cur * 16 * SA + (k8 + c) * SA + nb];
                bf[nt][1] = Bs[cur * 16 * SA + (k8 + c + 4) * SA + nb];
            }
#pragma unroll
            for (int mt = 0; mt < 2; ++mt)
#pragma unroll
                for (int nt = 0; nt < 4; ++nt) {
                    mma_tf32(acc_g[mt][nt], afg[mt], bf[nt]);
                    mma_tf32(acc_b[mt][nt], afb[mt], bf[nt]);
                }
        }
        if (more) STS_TILE_F(cur ^ 1);
        __syncthreads();
    }
#undef LDG_TILE_F
#undef STS_TILE_F

#pragma unroll
    for (int mt = 0; mt < 2; ++mt) {
#pragma unroll
        for (int h = 0; h < 2; ++h) {
            const int row = m0 + wm * 32 + mt * 16 + r + h * 8;
            float bg = bfilm[row];
            float bb = bfilm[256 + row];
#pragma unroll
            for (int nt = 0; nt < 4; ++nt) {
                const int col = n0 + wn * 32 + nt * 8 + c * 2;
                float g0  = acc_g[mt][nt][h * 2 + 0] + bg;
                float g1  = acc_g[mt][nt][h * 2 + 1] + bg;
                float be0 = acc_b[mt][nt][h * 2 + 0] + bb;
                float be1 = acc_b[mt][nt][h * 2 + 1] + bb;
                float2 xv = *(const float2*)&x[((size_t)bz * CH + row) * TT + col];
                float xmm0 = xmask[(size_t)bz * TT + col];
                float xmm1 = xmask[(size_t)bz * TT + col + 1];
                float2 o;
                o.x = (xv.x * g0 + be0) * xmm0;
                o.y = (xv.y * g1 + be1) * xmm1;
                *(float2*)&out[((size_t)bz * CH + row) * TT + col] = o;
            }
        }
    }
}

// ---------------- launch ----------------
extern "C" void kernel_launch(void* const* d_in, const int* in_sizes, int n_in,
                              void* d_out, int out_size) {
    const float* x           = (const float*)d_in[0];
    const float* x_mask      = (const float*)d_in[1];
    const float* cond_latent = (const float*)d_in[2];
    const float* cond_mask   = (const float*)d_in[3];
    const float* w_cond      = (const float*)d_in[4];
    const float* b_cond      = (const float*)d_in[5];
    const float* wq          = (const float*)d_in[6];
    const float* bq          = (const float*)d_in[7];
    const float* wk          = (const float*)d_in[8];
    const float* bk          = (const float*)d_in[9];
    const float* wv          = (const float*)d_in[10];
    const float* bv          = (const float*)d_in[11];
    const float* wo          = (const float*)d_in[12];
    const float* bo          = (const float*)d_in[13];
    const float* w_film      = (const float*)d_in[14];
    const float* b_film      = (const float*)d_in[15];
    float* out = (float*)d_out;

    float *p_c, *p_q, *p_k, *p_v, *p_att, *p_y, *p_xt, *p_cl, *p_wt;
    cudaGetSymbolAddress((void**)&p_c,   g_c);
    cudaGetSymbolAddress((void**)&p_q,   g_q);
    cudaGetSymbolAddress((void**)&p_k,   g_k);
    cudaGetSymbolAddress((void**)&p_v,   g_v);
    cudaGetSymbolAddress((void**)&p_att, g_att);
    cudaGetSymbolAddress((void**)&p_y,   g_y);
    cudaGetSymbolAddress((void**)&p_xt,  g_xt);
    cudaGetSymbolAddress((void**)&p_cl,  g_cl);
    cudaGetSymbolAddress((void**)&p_wt,  g_wt);

    cudaFuncSetAttribute(mma_gemm64<0>, cudaFuncAttributeMaxDynamicSharedMemorySize, GEMM_SMEM);
    cudaFuncSetAttribute(mma_gemm64<1>, cudaFuncAttributeMaxDynamicSharedMemorySize, GEMM_SMEM);
    cudaFuncSetAttribute(flash_attn,    cudaFuncAttributeMaxDynamicSharedMemorySize, FLASH_SMEM);
    cudaFuncSetAttribute(film_gemm,     cudaFuncAttributeMaxDynamicSharedMemorySize, FILM_SMEM);

    // RoPE tables + input pre-conversions (independent)
    rope_table_kernel<<<(32 * TT + 255) / 256, 256>>>();
    cvt_kernel<<<(BQ * CH * TT / 4 + 255) / 256, 256>>>(x, p_xt, BQ * CH * TT / 4);
    cvt_kernel<<<(BQ * CONDC * TSL / 4 + 255) / 256, 256>>>(cond_latent, p_cl, BQ * CONDC * TSL / 4);
    cvt_weights_kernel<<<dim3(128, 6), 256>>>(w_cond, wq, wk, wv, wo, w_film);

    // c = w_cond @ cond_latent + b_cond     -> tf32 bits
    mma_gemm64<0><<<dim3(TSL / 128, CH / 128, BQ), 256, GEMM_SMEM>>>(
        p_wt + W_COND, nullptr, p_cl, b_cond, nullptr, p_c, nullptr,
        TSL, CONDC, (size_t)CONDC * TSL, (size_t)CH * TSL, 1);

    // q = wq @ x + bq                       -> fp32 (rope_q converts)
    mma_gemm64<0><<<dim3(TT / 128, CH / 128, BQ), 256, GEMM_SMEM>>>(
        p_wt + W_Q, nullptr, p_xt, bq, nullptr, p_q, nullptr,
        TT, CH, (size_t)CH * TT, (size_t)CH * TT, 0);

    // k (fp32) and v (tf32 bits) fused
    mma_gemm64<1><<<dim3(TSL / 128, CH / 128, 2 * BQ), 256, GEMM_SMEM>>>(
        p_wt + W_K, p_wt + W_V, p_c, bk, bv, p_k, p_v,
        TSL, CH, (size_t)CH * TSL, (size_t)CH * TSL, 0);

    // rope + mask K -> tf32 bits; rope Q -> tf32 bits
    rope_k_mask_kernel<<<(BQ * NH * 32 * TSL + 255) / 256, 256>>>(p_k, cond_mask);
    rope_q_kernel<<<(BQ * NH * 32 * TT + 255) / 256, 256>>>(p_q);

    // fused attention -> att tf32 bits
    flash_attn<<<dim3(1, TT / 128, BQ * NH), 256, FLASH_SMEM>>>(
        p_q, p_k, p_v, cond_mask, p_att);

    // y = wo @ att + bo                     -> tf32 bits
    mma_gemm64<0><<<dim3(TT / 128, CH / 128, BQ), 256, GEMM_SMEM>>>(
        p_wt + W_O, nullptr, p_att, bo, nullptr, p_y, nullptr,
        TT, CH, (size_t)CH * TT, (size_t)CH * TT, 1);

    // fused FiLM (x stays fp32 for the elementwise part)
    film_gemm<<<dim3(TT / 128, CH / 128, BQ), 512, FILM_SMEM>>>(
        p_wt + W_FILM, p_y, b_film, x, x_mask, out);
}